// round 14
// baseline (speedup 1.0000x reference)
#include <cuda_runtime.h>
#include <cuda_bf16.h>
#include <math.h>

#define NV 200000
#define NE 50000
#define NNZp 2000000
#define FIN 256
#define DD 128

// ---------------- device scratch (no allocation allowed) ----------------
__device__ float g_x0[(size_t)NV * DD];
__device__ float g_x1[(size_t)NV * DD];
__device__ float g_y[(size_t)NE * DD];
__device__ int   g_cnt_e[NE];
__device__ int   g_cnt_v[NV];
__device__ float g_den_e[NE];
__device__ float g_den_v[NV];
__device__ float g_invdene[NE];
__device__ float g_invdenv[NV];
__device__ int   g_off_e[NE + 1];
__device__ int   g_off_v[NV + 1];
__device__ int   g_cur_e[NE + 1];
__device__ int   g_cur_v[NV + 1];
__device__ int   g_esrc[NNZp];
__device__ float g_ew[NNZp];
__device__ int   g_vsrc[NNZp];
__device__ float g_vw[NNZp];
__device__ int   g_scan_tmp[NV];
__device__ int   g_bsums[256];
__device__ __nv_bfloat16 g_Wth[DD * FIN];   // W transposed [n][k], hi part
__device__ __nv_bfloat16 g_Wtl[DD * FIN];   // W transposed [n][k], lo part

// ---------------- zero counters/denominators ----------------
__global__ void zero_small_kernel() {
    int i = blockIdx.x * blockDim.x + threadIdx.x;
    if (i < NE) { g_cnt_e[i] = 0; g_den_e[i] = 0.f; }
    if (i < NV) { g_cnt_v[i] = 0; g_den_v[i] = 0.f; }
}

// ---------------- histogram + denominators ----------------
__global__ void count_den_kernel(const int* __restrict__ pv, const int* __restrict__ pe,
                                 const float* __restrict__ wv2e, const float* __restrict__ we2v) {
    int i = blockIdx.x * blockDim.x + threadIdx.x;
    if (i >= NNZp) return;
    int v = pv[i], e = pe[i];
    atomicAdd(&g_cnt_e[e], 1);
    atomicAdd(&g_den_e[e], wv2e[i]);
    atomicAdd(&g_cnt_v[v], 1);
    atomicAdd(&g_den_v[v], we2v[i]);
}

__global__ void invden_kernel() {
    int i = blockIdx.x * blockDim.x + threadIdx.x;
    if (i < NE) g_invdene[i] = 1.f / fmaxf(g_den_e[i], 1e-12f);
    if (i < NV) g_invdenv[i] = 1.f / fmaxf(g_den_v[i], 1e-12f);
}

// ---------------- scan (1024 elems per block) ----------------
__global__ void scan_chunk_kernel(const int* __restrict__ in, int* __restrict__ incl,
                                  int* __restrict__ bsums, int n) {
    __shared__ int sh[256];
    int t = threadIdx.x;
    int base = blockIdx.x * 1024 + t * 4;
    int a0 = (base + 0 < n) ? in[base + 0] : 0;
    int a1 = (base + 1 < n) ? in[base + 1] : 0;
    int a2 = (base + 2 < n) ? in[base + 2] : 0;
    int a3 = (base + 3 < n) ? in[base + 3] : 0;
    int s1 = a0 + a1, s2 = s1 + a2, s3 = s2 + a3;
    sh[t] = s3;
    __syncthreads();
#pragma unroll
    for (int o = 1; o < 256; o <<= 1) {
        int v = (t >= o) ? sh[t - o] : 0;
        __syncthreads();
        sh[t] += v;
        __syncthreads();
    }
    int excl = sh[t] - s3;
    if (base + 0 < n) incl[base + 0] = excl + a0;
    if (base + 1 < n) incl[base + 1] = excl + s1;
    if (base + 2 < n) incl[base + 2] = excl + s2;
    if (base + 3 < n) incl[base + 3] = excl + s3;
    if (t == 255) bsums[blockIdx.x] = sh[255];
}

__global__ void scan_bsums_kernel(int* __restrict__ bsums, int nb) {
    __shared__ int sh[256];
    int t = threadIdx.x;
    int v = (t < nb) ? bsums[t] : 0;
    sh[t] = v;
    __syncthreads();
#pragma unroll
    for (int o = 1; o < 256; o <<= 1) {
        int u = (t >= o) ? sh[t - o] : 0;
        __syncthreads();
        sh[t] += u;
        __syncthreads();
    }
    if (t < nb) bsums[t] = sh[t] - v;   // exclusive
}

__global__ void finalize_off_kernel(const int* __restrict__ incl, const int* __restrict__ bexcl,
                                    int* __restrict__ off, int* __restrict__ cur, int n) {
    int i = blockIdx.x * blockDim.x + threadIdx.x;
    if (i >= n) return;
    int val = incl[i] + bexcl[i >> 10];
    off[i + 1] = val;
    cur[i + 1] = val;
    if (i == 0) { off[0] = 0; cur[0] = 0; }
}

// ---------------- fill CSR-style permuted arrays ----------------
__global__ void fill_kernel(const int* __restrict__ pv, const int* __restrict__ pe,
                            const float* __restrict__ wv2e, const float* __restrict__ we2v) {
    int i = blockIdx.x * blockDim.x + threadIdx.x;
    if (i >= NNZp) return;
    int v = pv[i], e = pe[i];
    int pe_pos = atomicAdd(&g_cur_e[e], 1);
    g_esrc[pe_pos] = v;
    g_ew[pe_pos]   = wv2e[i];
    int pv_pos = atomicAdd(&g_cur_v[v], 1);
    g_vsrc[pv_pos] = e;
    g_vw[pv_pos]   = we2v[i];
}

// ---------------- W prep: transpose + bf16 hi/lo split ----------------
__global__ void wprep_kernel(const float* __restrict__ Wm) {
    int i = blockIdx.x * blockDim.x + threadIdx.x;  // over DD*FIN
    if (i >= DD * FIN) return;
    int n = i / FIN, k = i % FIN;
    float w = Wm[(size_t)k * DD + n];
    __nv_bfloat16 hi = __float2bfloat16_rn(w);
    __nv_bfloat16 lo = __float2bfloat16_rn(w - __bfloat162float(hi));
    g_Wth[i] = hi;
    g_Wtl[i] = lo;
}

// ---------------- bf16-split tensor-core GEMM with ldmatrix:  x0 = feats @ W + b ----------------
// BM=128, BN=128(=DD), BK=32, 256 threads = 8 warps (4 m x 2 n), warp tile 32x64.
// C = Ah*Bh + Ah*Bl + Al*Bh  (fp32 accumulate; lo*lo dropped, err ~1e-5)
#define SK 40   // padded smem stride in halves (80B rows; 8-row ldmatrix bank-conflict-free)
#define NTILES (FIN / 32)

__device__ __forceinline__ void ldsm_x4(unsigned int& r0, unsigned int& r1,
                                        unsigned int& r2, unsigned int& r3,
                                        const __nv_bfloat16* p) {
    unsigned int addr = (unsigned int)__cvta_generic_to_shared(p);
    asm volatile("ldmatrix.sync.aligned.m8n8.x4.shared.b16 {%0,%1,%2,%3}, [%4];"
                 : "=r"(r0), "=r"(r1), "=r"(r2), "=r"(r3) : "r"(addr));
}

__global__ void __launch_bounds__(256) gemm_bf16_kernel(const float* __restrict__ A,
                                                        const float* __restrict__ bias,
                                                        float* __restrict__ C) {
    __shared__ __nv_bfloat16 Ah[128][SK], Al[128][SK];
    __shared__ __nv_bfloat16 Bh[128][SK], Bl[128][SK];

    const int tid  = threadIdx.x;
    const int lane = tid & 31;
    const int wid  = tid >> 5;
    const int warp_m = wid & 3;
    const int warp_n = wid >> 2;
    const int brow = blockIdx.x * 128;

    float acc[2][8][4];
#pragma unroll
    for (int mt = 0; mt < 2; mt++)
#pragma unroll
        for (int nt = 0; nt < 8; nt++)
#pragma unroll
            for (int q = 0; q < 4; q++) acc[mt][nt][q] = 0.f;

    // global-load lane mapping (A): id in [0,1024): row=id>>3, c=(id&7)*4
    const int arow0 = tid >> 3;             // +0, +32, +64, +96 via ii
    const int acol  = (tid & 7) * 4;
    // (B): id in [0,512): n=id>>2, seg=(id&3)*8
    const int bn    = tid >> 2;             // +0, +64 via ii (tid+ii*256 >>2)
    const int bseg  = (tid & 3) * 8;

    float4 pre_a[4];
    uint4  pre_bh[2], pre_bl[2];

    // ---- helpers as lambdas (inlined) ----
    auto load_global = [&](int k0) {
#pragma unroll
        for (int ii = 0; ii < 4; ii++) {
            int gr = brow + arow0 + ii * 32;
            pre_a[ii] = make_float4(0.f, 0.f, 0.f, 0.f);
            if (gr < NV) pre_a[ii] = *(const float4*)(A + (size_t)gr * FIN + k0 + acol);
        }
#pragma unroll
        for (int ii = 0; ii < 2; ii++) {
            int n = bn + ii * 64;
            pre_bh[ii] = *(const uint4*)&g_Wth[(size_t)n * FIN + k0 + bseg];
            pre_bl[ii] = *(const uint4*)&g_Wtl[(size_t)n * FIN + k0 + bseg];
        }
    };
    auto store_smem = [&]() {
#pragma unroll
        for (int ii = 0; ii < 4; ii++) {
            int row = arow0 + ii * 32;
            float4 v = pre_a[ii];
            __nv_bfloat16 hx = __float2bfloat16_rn(v.x);
            __nv_bfloat16 hy = __float2bfloat16_rn(v.y);
            __nv_bfloat16 hz = __float2bfloat16_rn(v.z);
            __nv_bfloat16 hw = __float2bfloat16_rn(v.w);
            __nv_bfloat16 lx = __float2bfloat16_rn(v.x - __bfloat162float(hx));
            __nv_bfloat16 ly = __float2bfloat16_rn(v.y - __bfloat162float(hy));
            __nv_bfloat16 lz = __float2bfloat16_rn(v.z - __bfloat162float(hz));
            __nv_bfloat16 lw = __float2bfloat16_rn(v.w - __bfloat162float(hw));
            *(__nv_bfloat162*)&Ah[row][acol]     = __halves2bfloat162(hx, hy);
            *(__nv_bfloat162*)&Ah[row][acol + 2] = __halves2bfloat162(hz, hw);
            *(__nv_bfloat162*)&Al[row][acol]     = __halves2bfloat162(lx, ly);
            *(__nv_bfloat162*)&Al[row][acol + 2] = __halves2bfloat162(lz, lw);
        }
#pragma unroll
        for (int ii = 0; ii < 2; ii++) {
            int n = bn + ii * 64;
            *(uint4*)&Bh[n][bseg] = pre_bh[ii];
            *(uint4*)&Bl[n][bseg] = pre_bl[ii];
        }
    };

    load_global(0);
    store_smem();
    __syncthreads();

    for (int t = 0; t < NTILES; t++) {
        if (t + 1 < NTILES) load_global((t + 1) * 32);

#pragma unroll
        for (int kk = 0; kk < 32; kk += 16) {
            // ---- A fragments via ldmatrix.x4: lanes 0-15 rows, lanes 16-31 k+8 half ----
            unsigned int ah[2][4], al[2][4];
#pragma unroll
            for (int mt = 0; mt < 2; mt++) {
                int r = warp_m * 32 + mt * 16 + (lane & 15);
                int c = kk + (lane >> 4) * 8;
                ldsm_x4(ah[mt][0], ah[mt][1], ah[mt][2], ah[mt][3], &Ah[r][c]);
                ldsm_x4(al[mt][0], al[mt][1], al[mt][2], al[mt][3], &Al[r][c]);
            }
            // ---- B fragments per 2-nt group via ldmatrix.x4 ----
#pragma unroll
            for (int ntp = 0; ntp < 4; ntp++) {
                int g = lane >> 3;                       // 0..3
                int n = warp_n * 64 + ntp * 16 + (g >> 1) * 8 + (lane & 7);
                int c = kk + (g & 1) * 8;
                unsigned int bh0a, bh1a, bh0b, bh1b;     // nt=2*ntp : b0,b1 ; nt=2*ntp+1 : b0,b1
                unsigned int bl0a, bl1a, bl0b, bl1b;
                ldsm_x4(bh0a, bh1a, bh0b, bh1b, &Bh[n][c]);
                ldsm_x4(bl0a, bl1a, bl0b, bl1b, &Bl[n][c]);
#pragma unroll
                for (int half = 0; half < 2; half++) {
                    int nt = ntp * 2 + half;
                    unsigned int bh0 = half ? bh0b : bh0a;
                    unsigned int bh1 = half ? bh1b : bh1a;
                    unsigned int bl0 = half ? bl0b : bl0a;
                    unsigned int bl1 = half ? bl1b : bl1a;
#pragma unroll
                    for (int mt = 0; mt < 2; mt++) {
                        float* d = acc[mt][nt];
                        asm volatile("mma.sync.aligned.m16n8k16.row.col.f32.bf16.bf16.f32 "
                            "{%0,%1,%2,%3}, {%4,%5,%6,%7}, {%8,%9}, {%0,%1,%2,%3};"
                            : "+f"(d[0]), "+f"(d[1]), "+f"(d[2]), "+f"(d[3])
                            : "r"(ah[mt][0]), "r"(ah[mt][1]), "r"(ah[mt][2]), "r"(ah[mt][3]),
                              "r"(bh0), "r"(bh1));
                        asm volatile("mma.sync.aligned.m16n8k16.row.col.f32.bf16.bf16.f32 "
                            "{%0,%1,%2,%3}, {%4,%5,%6,%7}, {%8,%9}, {%0,%1,%2,%3};"
                            : "+f"(d[0]), "+f"(d[1]), "+f"(d[2]), "+f"(d[3])
                            : "r"(ah[mt][0]), "r"(ah[mt][1]), "r"(ah[mt][2]), "r"(ah[mt][3]),
                              "r"(bl0), "r"(bl1));
                        asm volatile("mma.sync.aligned.m16n8k16.row.col.f32.bf16.bf16.f32 "
                            "{%0,%1,%2,%3}, {%4,%5,%6,%7}, {%8,%9}, {%0,%1,%2,%3};"
                            : "+f"(d[0]), "+f"(d[1]), "+f"(d[2]), "+f"(d[3])
                            : "r"(al[mt][0]), "r"(al[mt][1]), "r"(al[mt][2]), "r"(al[mt][3]),
                              "r"(bh0), "r"(bh1));
                    }
                }
            }
        }
        __syncthreads();
        if (t + 1 < NTILES) {
            store_smem();
            __syncthreads();
        }
    }

    const int rbase = brow + warp_m * 32 + (lane >> 2);
    const int cbase = warp_n * 64 + (lane & 3) * 2;
#pragma unroll
    for (int nt = 0; nt < 8; nt++) {
        int col = cbase + nt * 8;
        float b0 = __ldg(bias + col);
        float b1 = __ldg(bias + col + 1);
#pragma unroll
        for (int mt = 0; mt < 2; mt++) {
            int r0 = rbase + mt * 16;
            if (r0 < NV) {
                float2 o = make_float2(acc[mt][nt][0] + b0, acc[mt][nt][1] + b1);
                *(float2*)(C + (size_t)r0 * DD + col) = o;
            }
            int r1 = r0 + 8;
            if (r1 < NV) {
                float2 o = make_float2(acc[mt][nt][2] + b0, acc[mt][nt][3] + b1);
                *(float2*)(C + (size_t)r1 * DD + col) = o;
            }
        }
    }
}

// ---------------- gather-based weighted-mean aggregation ----------------
__global__ void __launch_bounds__(256) agg_kernel(const float4* __restrict__ src,
                                                  float4* __restrict__ dst,
                                                  const int* __restrict__ off,
                                                  const int* __restrict__ sidx,
                                                  const float* __restrict__ wt,
                                                  const float* __restrict__ invden,
                                                  int ndst) {
    int t = blockIdx.x * blockDim.x + threadIdx.x;
    int r = t >> 5;
    int lane = t & 31;
    if (r >= ndst) return;
    int j0 = __ldg(off + r);
    int j1 = __ldg(off + r + 1);
    float4 acc = make_float4(0.f, 0.f, 0.f, 0.f);
    int j = j0;
    for (; j + 2 <= j1; j += 2) {
        int   s0 = __ldg(sidx + j),   s1 = __ldg(sidx + j + 1);
        float w0 = __ldg(wt + j),     w1 = __ldg(wt + j + 1);
        float4 v0 = __ldg(src + (size_t)s0 * 32 + lane);
        float4 v1 = __ldg(src + (size_t)s1 * 32 + lane);
        acc.x = fmaf(w0, v0.x, acc.x); acc.y = fmaf(w0, v0.y, acc.y);
        acc.z = fmaf(w0, v0.z, acc.z); acc.w = fmaf(w0, v0.w, acc.w);
        acc.x = fmaf(w1, v1.x, acc.x); acc.y = fmaf(w1, v1.y, acc.y);
        acc.z = fmaf(w1, v1.z, acc.z); acc.w = fmaf(w1, v1.w, acc.w);
    }
    if (j < j1) {
        int   s0 = __ldg(sidx + j);
        float w0 = __ldg(wt + j);
        float4 v0 = __ldg(src + (size_t)s0 * 32 + lane);
        acc.x = fmaf(w0, v0.x, acc.x); acc.y = fmaf(w0, v0.y, acc.y);
        acc.z = fmaf(w0, v0.z, acc.z); acc.w = fmaf(w0, v0.w, acc.w);
    }
    float sc = __ldg(invden + r);
    acc.x *= sc; acc.y *= sc; acc.z *= sc; acc.w *= sc;
    dst[(size_t)r * 32 + lane] = acc;
}

// ---------------- final agg fused with softmax (row stays in registers) ----------------
__global__ void __launch_bounds__(256) agg_softmax_kernel(const float4* __restrict__ src,
                                                          float4* __restrict__ out,
                                                          const int* __restrict__ off,
                                                          const int* __restrict__ sidx,
                                                          const float* __restrict__ wt,
                                                          const float* __restrict__ invden) {
    int t = blockIdx.x * blockDim.x + threadIdx.x;
    int r = t >> 5;
    int lane = t & 31;
    if (r >= NV) return;
    int j0 = __ldg(off + r);
    int j1 = __ldg(off + r + 1);
    float4 acc = make_float4(0.f, 0.f, 0.f, 0.f);
    int j = j0;
    for (; j + 2 <= j1; j += 2) {
        int   s0 = __ldg(sidx + j),   s1 = __ldg(sidx + j + 1);
        float w0 = __ldg(wt + j),     w1 = __ldg(wt + j + 1);
        float4 v0 = __ldg(src + (size_t)s0 * 32 + lane);
        float4 v1 = __ldg(src + (size_t)s1 * 32 + lane);
        acc.x = fmaf(w0, v0.x, acc.x); acc.y = fmaf(w0, v0.y, acc.y);
        acc.z = fmaf(w0, v0.z, acc.z); acc.w = fmaf(w0, v0.w, acc.w);
        acc.x = fmaf(w1, v1.x, acc.x); acc.y = fmaf(w1, v1.y, acc.y);
        acc.z = fmaf(w1, v1.z, acc.z); acc.w = fmaf(w1, v1.w, acc.w);
    }
    if (j < j1) {
        int   s0 = __ldg(sidx + j);
        float w0 = __ldg(wt + j);
        float4 v0 = __ldg(src + (size_t)s0 * 32 + lane);
        acc.x = fmaf(w0, v0.x, acc.x); acc.y = fmaf(w0, v0.y, acc.y);
        acc.z = fmaf(w0, v0.z, acc.z); acc.w = fmaf(w0, v0.w, acc.w);
    }
    float sc = __ldg(invden + r);
    acc.x *= sc; acc.y *= sc; acc.z *= sc; acc.w *= sc;
    // warp softmax over the 128 values
    float m = fmaxf(fmaxf(acc.x, acc.y), fmaxf(acc.z, acc.w));
#pragma unroll
    for (int o = 16; o; o >>= 1) m = fmaxf(m, __shfl_xor_sync(0xffffffffu, m, o));
    float4 e;
    e.x = __expf(acc.x - m); e.y = __expf(acc.y - m);
    e.z = __expf(acc.z - m); e.w = __expf(acc.w - m);
    float s = e.x + e.y + e.z + e.w;
#pragma unroll
    for (int o = 16; o; o >>= 1) s += __shfl_xor_sync(0xffffffffu, s, o);
    float inv = 1.f / s;
    out[(size_t)r * 32 + lane] = make_float4(e.x * inv, e.y * inv, e.z * inv, e.w * inv);
}

// ---------------- launch ----------------
extern "C" void kernel_launch(void* const* d_in, const int* in_sizes, int n_in,
                              void* d_out, int out_size) {
    const float* feats = (const float*)d_in[0];
    const float* Wm    = (const float*)d_in[1];
    const float* bias  = (const float*)d_in[2];
    const float* v2e_w = (const float*)d_in[3];
    const float* e2v_w = (const float*)d_in[4];
    const int*   pv    = (const int*)d_in[5];
    const int*   pe    = (const int*)d_in[6];
    float* out = (float*)d_out;

    float *x0, *x1, *y, *invdene, *invdenv, *ew, *vw;
    int *cnt_e, *cnt_v, *off_e, *off_v, *cur_e, *cur_v, *esrc, *vsrc, *scan_tmp, *bsums;
    cudaGetSymbolAddress((void**)&x0, g_x0);
    cudaGetSymbolAddress((void**)&x1, g_x1);
    cudaGetSymbolAddress((void**)&y,  g_y);
    cudaGetSymbolAddress((void**)&invdene, g_invdene);
    cudaGetSymbolAddress((void**)&invdenv, g_invdenv);
    cudaGetSymbolAddress((void**)&ew, g_ew);
    cudaGetSymbolAddress((void**)&vw, g_vw);
    cudaGetSymbolAddress((void**)&cnt_e, g_cnt_e);
    cudaGetSymbolAddress((void**)&cnt_v, g_cnt_v);
    cudaGetSymbolAddress((void**)&off_e, g_off_e);
    cudaGetSymbolAddress((void**)&off_v, g_off_v);
    cudaGetSymbolAddress((void**)&cur_e, g_cur_e);
    cudaGetSymbolAddress((void**)&cur_v, g_cur_v);
    cudaGetSymbolAddress((void**)&esrc, g_esrc);
    cudaGetSymbolAddress((void**)&vsrc, g_vsrc);
    cudaGetSymbolAddress((void**)&scan_tmp, g_scan_tmp);
    cudaGetSymbolAddress((void**)&bsums, g_bsums);

    const int TB = 256;
    const int nnzBlocks = (NNZp + TB - 1) / TB;

    // Fork a side stream for the CSR build chain; GEMM runs on the main (captured)
    // stream concurrently. Standard capture-fork: event edges define the graph deps.
    cudaStream_t s2;
    cudaStreamCreateWithFlags(&s2, cudaStreamNonBlocking);
    cudaEvent_t evFork, evJoin;
    cudaEventCreateWithFlags(&evFork, cudaEventDisableTiming);
    cudaEventCreateWithFlags(&evJoin, cudaEventDisableTiming);

    cudaEventRecord(evFork, 0);
    cudaStreamWaitEvent(s2, evFork, 0);

    // ---- branch A (s2): CSR build ----
    zero_small_kernel<<<(NV + TB - 1) / TB, TB, 0, s2>>>();
    count_den_kernel<<<nnzBlocks, TB, 0, s2>>>(pv, pe, v2e_w, e2v_w);
    invden_kernel<<<(NV + TB - 1) / TB, TB, 0, s2>>>();
    {
        int nb = (NE + 1023) / 1024;
        scan_chunk_kernel<<<nb, 256, 0, s2>>>(cnt_e, scan_tmp, bsums, NE);
        scan_bsums_kernel<<<1, 256, 0, s2>>>(bsums, nb);
        finalize_off_kernel<<<(NE + TB - 1) / TB, TB, 0, s2>>>(scan_tmp, bsums, off_e, cur_e, NE);
    }
    {
        int nb = (NV + 1023) / 1024;
        scan_chunk_kernel<<<nb, 256, 0, s2>>>(cnt_v, scan_tmp, bsums, NV);
        scan_bsums_kernel<<<1, 256, 0, s2>>>(bsums, nb);
        finalize_off_kernel<<<(NV + TB - 1) / TB, TB, 0, s2>>>(scan_tmp, bsums, off_v, cur_v, NV);
    }
    fill_kernel<<<nnzBlocks, TB, 0, s2>>>(pv, pe, v2e_w, e2v_w);

    // ---- branch B (main stream): W prep + GEMM ----
    wprep_kernel<<<(DD * FIN + TB - 1) / TB, TB>>>(Wm);
    gemm_bf16_kernel<<<(NV + 127) / 128, TB>>>(feats, bias, x0);

    // ---- join ----
    cudaEventRecord(evJoin, s2);
    cudaStreamWaitEvent(0, evJoin, 0);

    // 5) two hops of weighted-mean aggregation; last pass fused with softmax
    const int eBlocks = (NE * 32) / TB;
    const int vBlocks = (NV * 32) / TB;
    agg_kernel<<<eBlocks, TB>>>((const float4*)x0, (float4*)y,  off_e, esrc, ew, invdene, NE);
    agg_kernel<<<vBlocks, TB>>>((const float4*)y,  (float4*)x1, off_v, vsrc, vw, invdenv, NV);
    agg_kernel<<<eBlocks, TB>>>((const float4*)x1, (float4*)y,  off_e, esrc, ew, invdene, NE);
    agg_softmax_kernel<<<vBlocks, TB>>>((const float4*)y, (float4*)out, off_v, vsrc, vw, invdenv);
}

// round 15
// speedup vs baseline: 1.1920x; 1.1920x over previous
#include <cuda_runtime.h>
#include <cuda_bf16.h>
#include <cuda_fp16.h>
#include <math.h>

#define NV 200000
#define NE 50000
#define NNZp 2000000
#define FIN 256
#define DD 128

// ---------------- device scratch (no allocation allowed) ----------------
__device__ __half g_xh0[(size_t)NV * DD];   // GEMM output (fp16)
__device__ __half g_x1h[(size_t)NV * DD];   // intermediate vertex features (fp16)
__device__ __half g_yh[(size_t)NE * DD];    // edge features (fp16)
__device__ int   g_cnt_e[NE];
__device__ int   g_cnt_v[NV];
__device__ float g_den_e[NE];
__device__ float g_den_v[NV];
__device__ float g_invdene[NE];
__device__ float g_invdenv[NV];
__device__ int   g_off_e[NE + 1];
__device__ int   g_off_v[NV + 1];
__device__ int   g_cur_e[NE + 1];
__device__ int   g_cur_v[NV + 1];
__device__ int   g_esrc[NNZp];
__device__ float g_ew[NNZp];
__device__ int   g_vsrc[NNZp];
__device__ float g_vw[NNZp];
__device__ int   g_scan_tmp[NV];
__device__ int   g_bsums[256];
__device__ __nv_bfloat16 g_Wth[DD * FIN];   // W transposed [n][k], hi part
__device__ __nv_bfloat16 g_Wtl[DD * FIN];   // W transposed [n][k], lo part

// ---------------- fp16 <-> fp32 pack helpers ----------------
__device__ __forceinline__ float4 h4_to_f4(uint2 u) {
    __half2 a = *reinterpret_cast<__half2*>(&u.x);
    __half2 b = *reinterpret_cast<__half2*>(&u.y);
    float2 fa = __half22float2(a), fb = __half22float2(b);
    return make_float4(fa.x, fa.y, fb.x, fb.y);
}
__device__ __forceinline__ uint2 f4_to_h4(float4 v) {
    __half2 a = __floats2half2_rn(v.x, v.y);
    __half2 b = __floats2half2_rn(v.z, v.w);
    uint2 u;
    u.x = *reinterpret_cast<unsigned int*>(&a);
    u.y = *reinterpret_cast<unsigned int*>(&b);
    return u;
}

// ---------------- zero counters/denominators ----------------
__global__ void zero_small_kernel() {
    int i = blockIdx.x * blockDim.x + threadIdx.x;
    if (i < NE) { g_cnt_e[i] = 0; g_den_e[i] = 0.f; }
    if (i < NV) { g_cnt_v[i] = 0; g_den_v[i] = 0.f; }
}

// ---------------- histogram + denominators ----------------
__global__ void count_den_kernel(const int* __restrict__ pv, const int* __restrict__ pe,
                                 const float* __restrict__ wv2e, const float* __restrict__ we2v) {
    int i = blockIdx.x * blockDim.x + threadIdx.x;
    if (i >= NNZp) return;
    int v = pv[i], e = pe[i];
    atomicAdd(&g_cnt_e[e], 1);
    atomicAdd(&g_den_e[e], wv2e[i]);
    atomicAdd(&g_cnt_v[v], 1);
    atomicAdd(&g_den_v[v], we2v[i]);
}

__global__ void invden_kernel() {
    int i = blockIdx.x * blockDim.x + threadIdx.x;
    if (i < NE) g_invdene[i] = 1.f / fmaxf(g_den_e[i], 1e-12f);
    if (i < NV) g_invdenv[i] = 1.f / fmaxf(g_den_v[i], 1e-12f);
}

// ---------------- scan (1024 elems per block) ----------------
__global__ void scan_chunk_kernel(const int* __restrict__ in, int* __restrict__ incl,
                                  int* __restrict__ bsums, int n) {
    __shared__ int sh[256];
    int t = threadIdx.x;
    int base = blockIdx.x * 1024 + t * 4;
    int a0 = (base + 0 < n) ? in[base + 0] : 0;
    int a1 = (base + 1 < n) ? in[base + 1] : 0;
    int a2 = (base + 2 < n) ? in[base + 2] : 0;
    int a3 = (base + 3 < n) ? in[base + 3] : 0;
    int s1 = a0 + a1, s2 = s1 + a2, s3 = s2 + a3;
    sh[t] = s3;
    __syncthreads();
#pragma unroll
    for (int o = 1; o < 256; o <<= 1) {
        int v = (t >= o) ? sh[t - o] : 0;
        __syncthreads();
        sh[t] += v;
        __syncthreads();
    }
    int excl = sh[t] - s3;
    if (base + 0 < n) incl[base + 0] = excl + a0;
    if (base + 1 < n) incl[base + 1] = excl + s1;
    if (base + 2 < n) incl[base + 2] = excl + s2;
    if (base + 3 < n) incl[base + 3] = excl + s3;
    if (t == 255) bsums[blockIdx.x] = sh[255];
}

__global__ void scan_bsums_kernel(int* __restrict__ bsums, int nb) {
    __shared__ int sh[256];
    int t = threadIdx.x;
    int v = (t < nb) ? bsums[t] : 0;
    sh[t] = v;
    __syncthreads();
#pragma unroll
    for (int o = 1; o < 256; o <<= 1) {
        int u = (t >= o) ? sh[t - o] : 0;
        __syncthreads();
        sh[t] += u;
        __syncthreads();
    }
    if (t < nb) bsums[t] = sh[t] - v;   // exclusive
}

__global__ void finalize_off_kernel(const int* __restrict__ incl, const int* __restrict__ bexcl,
                                    int* __restrict__ off, int* __restrict__ cur, int n) {
    int i = blockIdx.x * blockDim.x + threadIdx.x;
    if (i >= n) return;
    int val = incl[i] + bexcl[i >> 10];
    off[i + 1] = val;
    cur[i + 1] = val;
    if (i == 0) { off[0] = 0; cur[0] = 0; }
}

// ---------------- fill CSR-style permuted arrays ----------------
__global__ void fill_kernel(const int* __restrict__ pv, const int* __restrict__ pe,
                            const float* __restrict__ wv2e, const float* __restrict__ we2v) {
    int i = blockIdx.x * blockDim.x + threadIdx.x;
    if (i >= NNZp) return;
    int v = pv[i], e = pe[i];
    int pe_pos = atomicAdd(&g_cur_e[e], 1);
    g_esrc[pe_pos] = v;
    g_ew[pe_pos]   = wv2e[i];
    int pv_pos = atomicAdd(&g_cur_v[v], 1);
    g_vsrc[pv_pos] = e;
    g_vw[pv_pos]   = we2v[i];
}

// ---------------- W prep: transpose + bf16 hi/lo split ----------------
__global__ void wprep_kernel(const float* __restrict__ Wm) {
    int i = blockIdx.x * blockDim.x + threadIdx.x;  // over DD*FIN
    if (i >= DD * FIN) return;
    int n = i / FIN, k = i % FIN;
    float w = Wm[(size_t)k * DD + n];
    __nv_bfloat16 hi = __float2bfloat16_rn(w);
    __nv_bfloat16 lo = __float2bfloat16_rn(w - __bfloat162float(hi));
    g_Wth[i] = hi;
    g_Wtl[i] = lo;
}

// ---------------- bf16-split tensor-core GEMM:  xh0 = fp16(feats @ W + b) ----------------
// BM=128, BN=128(=DD), BK=32, 256 threads = 8 warps (4 m x 2 n), warp tile 32x64.
// C = Ah*Bh + Ah*Bl + Al*Bh  (fp32 accumulate; lo*lo dropped, err ~1e-5)
#define SK 40   // padded smem stride in halves (conflict-free)
__global__ void __launch_bounds__(256) gemm_bf16_kernel(const float* __restrict__ A,
                                                        const float* __restrict__ bias,
                                                        __half* __restrict__ C) {
    __shared__ __nv_bfloat16 Ah[128][SK], Al[128][SK];
    __shared__ __nv_bfloat16 Bh[128][SK], Bl[128][SK];

    const int tid  = threadIdx.x;
    const int lane = tid & 31;
    const int wid  = tid >> 5;
    const int warp_m = wid & 3;
    const int warp_n = wid >> 2;
    const int brow = blockIdx.x * 128;

    float acc[2][8][4];
#pragma unroll
    for (int mt = 0; mt < 2; mt++)
#pragma unroll
        for (int nt = 0; nt < 8; nt++)
#pragma unroll
            for (int q = 0; q < 4; q++) acc[mt][nt][q] = 0.f;

    for (int k0 = 0; k0 < FIN; k0 += 32) {
#pragma unroll
        for (int ii = 0; ii < 4; ii++) {
            int id  = tid + ii * 256;
            int row = id >> 3;
            int c   = (id & 7) * 4;
            int gr  = brow + row;
            float4 v = make_float4(0.f, 0.f, 0.f, 0.f);
            if (gr < NV) v = *(const float4*)(A + (size_t)gr * FIN + k0 + c);
            __nv_bfloat16 hx = __float2bfloat16_rn(v.x);
            __nv_bfloat16 hy = __float2bfloat16_rn(v.y);
            __nv_bfloat16 hz = __float2bfloat16_rn(v.z);
            __nv_bfloat16 hw = __float2bfloat16_rn(v.w);
            __nv_bfloat16 lx = __float2bfloat16_rn(v.x - __bfloat162float(hx));
            __nv_bfloat16 ly = __float2bfloat16_rn(v.y - __bfloat162float(hy));
            __nv_bfloat16 lz = __float2bfloat16_rn(v.z - __bfloat162float(hz));
            __nv_bfloat16 lw = __float2bfloat16_rn(v.w - __bfloat162float(hw));
            *(__nv_bfloat162*)&Ah[row][c]     = __halves2bfloat162(hx, hy);
            *(__nv_bfloat162*)&Ah[row][c + 2] = __halves2bfloat162(hz, hw);
            *(__nv_bfloat162*)&Al[row][c]     = __halves2bfloat162(lx, ly);
            *(__nv_bfloat162*)&Al[row][c + 2] = __halves2bfloat162(lz, lw);
        }
#pragma unroll
        for (int ii = 0; ii < 2; ii++) {
            int id  = tid + ii * 256;
            int n   = id >> 2;
            int seg = (id & 3) * 8;
            *(uint4*)&Bh[n][seg] = *(const uint4*)&g_Wth[(size_t)n * FIN + k0 + seg];
            *(uint4*)&Bl[n][seg] = *(const uint4*)&g_Wtl[(size_t)n * FIN + k0 + seg];
        }
        __syncthreads();

#pragma unroll
        for (int kk = 0; kk < 32; kk += 16) {
            const int c0 = kk + (lane & 3) * 2;
            const int ra = warp_m * 32 + (lane >> 2);
            unsigned int ah[2][4], al[2][4];
#pragma unroll
            for (int mt = 0; mt < 2; mt++) {
                int r = ra + mt * 16;
                ah[mt][0] = *(const unsigned int*)&Ah[r][c0];
                ah[mt][1] = *(const unsigned int*)&Ah[r + 8][c0];
                ah[mt][2] = *(const unsigned int*)&Ah[r][c0 + 8];
                ah[mt][3] = *(const unsigned int*)&Ah[r + 8][c0 + 8];
                al[mt][0] = *(const unsigned int*)&Al[r][c0];
                al[mt][1] = *(const unsigned int*)&Al[r + 8][c0];
                al[mt][2] = *(const unsigned int*)&Al[r][c0 + 8];
                al[mt][3] = *(const unsigned int*)&Al[r + 8][c0 + 8];
            }
#pragma unroll
            for (int nt = 0; nt < 8; nt++) {
                int n = warp_n * 64 + nt * 8 + (lane >> 2);
                unsigned int bh0 = *(const unsigned int*)&Bh[n][c0];
                unsigned int bh1 = *(const unsigned int*)&Bh[n][c0 + 8];
                unsigned int bl0 = *(const unsigned int*)&Bl[n][c0];
                unsigned int bl1 = *(const unsigned int*)&Bl[n][c0 + 8];
#pragma unroll
                for (int mt = 0; mt < 2; mt++) {
                    float* d = acc[mt][nt];
                    asm volatile("mma.sync.aligned.m16n8k16.row.col.f32.bf16.bf16.f32 "
                        "{%0,%1,%2,%3}, {%4,%5,%6,%7}, {%8,%9}, {%0,%1,%2,%3};"
                        : "+f"(d[0]), "+f"(d[1]), "+f"(d[2]), "+f"(d[3])
                        : "r"(ah[mt][0]), "r"(ah[mt][1]), "r"(ah[mt][2]), "r"(ah[mt][3]),
                          "r"(bh0), "r"(bh1));
                    asm volatile("mma.sync.aligned.m16n8k16.row.col.f32.bf16.bf16.f32 "
                        "{%0,%1,%2,%3}, {%4,%5,%6,%7}, {%8,%9}, {%0,%1,%2,%3};"
                        : "+f"(d[0]), "+f"(d[1]), "+f"(d[2]), "+f"(d[3])
                        : "r"(ah[mt][0]), "r"(ah[mt][1]), "r"(ah[mt][2]), "r"(ah[mt][3]),
                          "r"(bl0), "r"(bl1));
                    asm volatile("mma.sync.aligned.m16n8k16.row.col.f32.bf16.bf16.f32 "
                        "{%0,%1,%2,%3}, {%4,%5,%6,%7}, {%8,%9}, {%0,%1,%2,%3};"
                        : "+f"(d[0]), "+f"(d[1]), "+f"(d[2]), "+f"(d[3])
                        : "r"(al[mt][0]), "r"(al[mt][1]), "r"(al[mt][2]), "r"(al[mt][3]),
                          "r"(bh0), "r"(bh1));
                }
            }
        }
        __syncthreads();
    }

    const int rbase = brow + warp_m * 32 + (lane >> 2);
    const int cbase = warp_n * 64 + (lane & 3) * 2;
#pragma unroll
    for (int nt = 0; nt < 8; nt++) {
        int col = cbase + nt * 8;
        float b0 = __ldg(bias + col);
        float b1 = __ldg(bias + col + 1);
#pragma unroll
        for (int mt = 0; mt < 2; mt++) {
            int r0 = rbase + mt * 16;
            if (r0 < NV) {
                __half2 o = __floats2half2_rn(acc[mt][nt][0] + b0, acc[mt][nt][1] + b1);
                *(__half2*)(C + (size_t)r0 * DD + col) = o;
            }
            int r1 = r0 + 8;
            if (r1 < NV) {
                __half2 o = __floats2half2_rn(acc[mt][nt][2] + b0, acc[mt][nt][3] + b1);
                *(__half2*)(C + (size_t)r1 * DD + col) = o;
            }
        }
    }
}

// ---------------- gather-based weighted-mean aggregation (fp16 src/dst, fp32 math) ----------------
__global__ void __launch_bounds__(256) agg_kernel_h(const __half* __restrict__ src,
                                                    __half* __restrict__ dst,
                                                    const int* __restrict__ off,
                                                    const int* __restrict__ sidx,
                                                    const float* __restrict__ wt,
                                                    const float* __restrict__ invden,
                                                    int ndst) {
    int t = blockIdx.x * blockDim.x + threadIdx.x;
    int r = t >> 5;
    int lane = t & 31;
    if (r >= ndst) return;
    int j0 = __ldg(off + r);
    int j1 = __ldg(off + r + 1);
    float4 acc = make_float4(0.f, 0.f, 0.f, 0.f);
    const int cofs = lane * 4;
    int j = j0;
    for (; j + 2 <= j1; j += 2) {
        int   s0 = __ldg(sidx + j),   s1 = __ldg(sidx + j + 1);
        float w0 = __ldg(wt + j),     w1 = __ldg(wt + j + 1);
        float4 v0 = h4_to_f4(*(const uint2*)(src + (size_t)s0 * DD + cofs));
        float4 v1 = h4_to_f4(*(const uint2*)(src + (size_t)s1 * DD + cofs));
        acc.x = fmaf(w0, v0.x, acc.x); acc.y = fmaf(w0, v0.y, acc.y);
        acc.z = fmaf(w0, v0.z, acc.z); acc.w = fmaf(w0, v0.w, acc.w);
        acc.x = fmaf(w1, v1.x, acc.x); acc.y = fmaf(w1, v1.y, acc.y);
        acc.z = fmaf(w1, v1.z, acc.z); acc.w = fmaf(w1, v1.w, acc.w);
    }
    if (j < j1) {
        int   s0 = __ldg(sidx + j);
        float w0 = __ldg(wt + j);
        float4 v0 = h4_to_f4(*(const uint2*)(src + (size_t)s0 * DD + cofs));
        acc.x = fmaf(w0, v0.x, acc.x); acc.y = fmaf(w0, v0.y, acc.y);
        acc.z = fmaf(w0, v0.z, acc.z); acc.w = fmaf(w0, v0.w, acc.w);
    }
    float sc = __ldg(invden + r);
    acc.x *= sc; acc.y *= sc; acc.z *= sc; acc.w *= sc;
    *(uint2*)(dst + (size_t)r * DD + cofs) = f4_to_h4(acc);
}

// ---------------- final agg fused with softmax (fp16 src, fp32 out) ----------------
__global__ void __launch_bounds__(256) agg_softmax_kernel_h(const __half* __restrict__ src,
                                                            float4* __restrict__ out,
                                                            const int* __restrict__ off,
                                                            const int* __restrict__ sidx,
                                                            const float* __restrict__ wt,
                                                            const float* __restrict__ invden) {
    int t = blockIdx.x * blockDim.x + threadIdx.x;
    int r = t >> 5;
    int lane = t & 31;
    if (r >= NV) return;
    int j0 = __ldg(off + r);
    int j1 = __ldg(off + r + 1);
    float4 acc = make_float4(0.f, 0.f, 0.f, 0.f);
    const int cofs = lane * 4;
    int j = j0;
    for (; j + 2 <= j1; j += 2) {
        int   s0 = __ldg(sidx + j),   s1 = __ldg(sidx + j + 1);
        float w0 = __ldg(wt + j),     w1 = __ldg(wt + j + 1);
        float4 v0 = h4_to_f4(*(const uint2*)(src + (size_t)s0 * DD + cofs));
        float4 v1 = h4_to_f4(*(const uint2*)(src + (size_t)s1 * DD + cofs));
        acc.x = fmaf(w0, v0.x, acc.x); acc.y = fmaf(w0, v0.y, acc.y);
        acc.z = fmaf(w0, v0.z, acc.z); acc.w = fmaf(w0, v0.w, acc.w);
        acc.x = fmaf(w1, v1.x, acc.x); acc.y = fmaf(w1, v1.y, acc.y);
        acc.z = fmaf(w1, v1.z, acc.z); acc.w = fmaf(w1, v1.w, acc.w);
    }
    if (j < j1) {
        int   s0 = __ldg(sidx + j);
        float w0 = __ldg(wt + j);
        float4 v0 = h4_to_f4(*(const uint2*)(src + (size_t)s0 * DD + cofs));
        acc.x = fmaf(w0, v0.x, acc.x); acc.y = fmaf(w0, v0.y, acc.y);
        acc.z = fmaf(w0, v0.z, acc.z); acc.w = fmaf(w0, v0.w, acc.w);
    }
    float sc = __ldg(invden + r);
    acc.x *= sc; acc.y *= sc; acc.z *= sc; acc.w *= sc;
    // warp softmax over the 128 values
    float m = fmaxf(fmaxf(acc.x, acc.y), fmaxf(acc.z, acc.w));
#pragma unroll
    for (int o = 16; o; o >>= 1) m = fmaxf(m, __shfl_xor_sync(0xffffffffu, m, o));
    float4 e;
    e.x = __expf(acc.x - m); e.y = __expf(acc.y - m);
    e.z = __expf(acc.z - m); e.w = __expf(acc.w - m);
    float s = e.x + e.y + e.z + e.w;
#pragma unroll
    for (int o = 16; o; o >>= 1) s += __shfl_xor_sync(0xffffffffu, s, o);
    float inv = 1.f / s;
    out[(size_t)r * 32 + lane] = make_float4(e.x * inv, e.y * inv, e.z * inv, e.w * inv);
}

// ---------------- launch ----------------
extern "C" void kernel_launch(void* const* d_in, const int* in_sizes, int n_in,
                              void* d_out, int out_size) {
    const float* feats = (const float*)d_in[0];
    const float* Wm    = (const float*)d_in[1];
    const float* bias  = (const float*)d_in[2];
    const float* v2e_w = (const float*)d_in[3];
    const float* e2v_w = (const float*)d_in[4];
    const int*   pv    = (const int*)d_in[5];
    const int*   pe    = (const int*)d_in[6];
    float* out = (float*)d_out;

    __half *xh0, *x1h, *yh;
    float *invdene, *invdenv, *ew, *vw;
    int *cnt_e, *cnt_v, *off_e, *off_v, *cur_e, *cur_v, *esrc, *vsrc, *scan_tmp, *bsums;
    cudaGetSymbolAddress((void**)&xh0, g_xh0);
    cudaGetSymbolAddress((void**)&x1h, g_x1h);
    cudaGetSymbolAddress((void**)&yh,  g_yh);
    cudaGetSymbolAddress((void**)&invdene, g_invdene);
    cudaGetSymbolAddress((void**)&invdenv, g_invdenv);
    cudaGetSymbolAddress((void**)&ew, g_ew);
    cudaGetSymbolAddress((void**)&vw, g_vw);
    cudaGetSymbolAddress((void**)&cnt_e, g_cnt_e);
    cudaGetSymbolAddress((void**)&cnt_v, g_cnt_v);
    cudaGetSymbolAddress((void**)&off_e, g_off_e);
    cudaGetSymbolAddress((void**)&off_v, g_off_v);
    cudaGetSymbolAddress((void**)&cur_e, g_cur_e);
    cudaGetSymbolAddress((void**)&cur_v, g_cur_v);
    cudaGetSymbolAddress((void**)&esrc, g_esrc);
    cudaGetSymbolAddress((void**)&vsrc, g_vsrc);
    cudaGetSymbolAddress((void**)&scan_tmp, g_scan_tmp);
    cudaGetSymbolAddress((void**)&bsums, g_bsums);

    const int TB = 256;
    const int nnzBlocks = (NNZp + TB - 1) / TB;

    // Fork a side stream for the CSR build chain; GEMM runs on the main (captured)
    // stream concurrently. Standard capture-fork: event edges define the graph deps.
    cudaStream_t s2;
    cudaStreamCreateWithFlags(&s2, cudaStreamNonBlocking);
    cudaEvent_t evFork, evJoin;
    cudaEventCreateWithFlags(&evFork, cudaEventDisableTiming);
    cudaEventCreateWithFlags(&evJoin, cudaEventDisableTiming);

    cudaEventRecord(evFork, 0);
    cudaStreamWaitEvent(s2, evFork, 0);

    // ---- branch A (s2): CSR build ----
    zero_small_kernel<<<(NV + TB - 1) / TB, TB, 0, s2>>>();
    count_den_kernel<<<nnzBlocks, TB, 0, s2>>>(pv, pe, v2e_w, e2v_w);
    invden_kernel<<<(NV + TB - 1) / TB, TB, 0, s2>>>();
    {
        int nb = (NE + 1023) / 1024;
        scan_chunk_kernel<<<nb, 256, 0, s2>>>(cnt_e, scan_tmp, bsums, NE);
        scan_bsums_kernel<<<1, 256, 0, s2>>>(bsums, nb);
        finalize_off_kernel<<<(NE + TB - 1) / TB, TB, 0, s2>>>(scan_tmp, bsums, off_e, cur_e, NE);
    }
    {
        int nb = (NV + 1023) / 1024;
        scan_chunk_kernel<<<nb, 256, 0, s2>>>(cnt_v, scan_tmp, bsums, NV);
        scan_bsums_kernel<<<1, 256, 0, s2>>>(bsums, nb);
        finalize_off_kernel<<<(NV + TB - 1) / TB, TB, 0, s2>>>(scan_tmp, bsums, off_v, cur_v, NV);
    }
    fill_kernel<<<nnzBlocks, TB, 0, s2>>>(pv, pe, v2e_w, e2v_w);

    // ---- branch B (main stream): W prep + GEMM ----
    wprep_kernel<<<(DD * FIN + TB - 1) / TB, TB>>>(Wm);
    gemm_bf16_kernel<<<(NV + 127) / 128, TB>>>(feats, bias, xh0);

    // ---- join ----
    cudaEventRecord(evJoin, s2);
    cudaStreamWaitEvent(0, evJoin, 0);

    // 5) two hops of weighted-mean aggregation (fp16 features, fp32 math);
    //    last pass fused with softmax
    const int eBlocks = (NE * 32) / TB;
    const int vBlocks = (NV * 32) / TB;
    agg_kernel_h<<<eBlocks, TB>>>(xh0, yh,  off_e, esrc, ew, invdene, NE);
    agg_kernel_h<<<vBlocks, TB>>>(yh,  x1h, off_v, vsrc, vw, invdenv, NV);
    agg_kernel_h<<<eBlocks, TB>>>(x1h, yh,  off_e, esrc, ew, invdene, NE);
    agg_softmax_kernel_h<<<vBlocks, TB>>>(yh, (float4*)out, off_v, vsrc, vw, invdenv);
}

// round 17
// speedup vs baseline: 1.2222x; 1.0253x over previous
#include <cuda_runtime.h>
#include <cuda_bf16.h>
#include <cuda_fp16.h>
#include <math.h>

#define NV 200000
#define NE 50000
#define NNZp 2000000
#define FIN 256
#define DD 128

// ---------------- device scratch (no allocation allowed) ----------------
__device__ __half g_xh0[(size_t)NV * DD];   // GEMM output (fp16)
__device__ __half g_x1h[(size_t)NV * DD];   // intermediate vertex features (fp16)
__device__ __half g_yh[(size_t)NE * DD];    // edge features (fp16)
__device__ int   g_cnt_e[NE];
__device__ int   g_cnt_v[NV];
__device__ float g_den_e[NE];
__device__ float g_den_v[NV];
__device__ float g_invdene[NE];
__device__ float g_invdenv[NV];
__device__ int   g_off_e[NE + 1];
__device__ int   g_off_v[NV + 1];
__device__ int   g_cur_e[NE + 1];
__device__ int   g_cur_v[NV + 1];
__device__ int   g_esrc[NNZp];
__device__ float g_ew[NNZp];
__device__ int   g_vsrc[NNZp];
__device__ float g_vw[NNZp];
__device__ int   g_scan_tmp[NV];
__device__ int   g_bsums[256];
__device__ __nv_bfloat16 g_Wth[DD * FIN];   // W transposed [n][k], hi part
__device__ __nv_bfloat16 g_Wtl[DD * FIN];   // W transposed [n][k], lo part

// ---------------- fp16 <-> fp32 pack helpers ----------------
__device__ __forceinline__ float4 h4_to_f4(uint2 u) {
    __half2 a = *reinterpret_cast<__half2*>(&u.x);
    __half2 b = *reinterpret_cast<__half2*>(&u.y);
    float2 fa = __half22float2(a), fb = __half22float2(b);
    return make_float4(fa.x, fa.y, fb.x, fb.y);
}
__device__ __forceinline__ uint2 f4_to_h4(float4 v) {
    __half2 a = __floats2half2_rn(v.x, v.y);
    __half2 b = __floats2half2_rn(v.z, v.w);
    uint2 u;
    u.x = *reinterpret_cast<unsigned int*>(&a);
    u.y = *reinterpret_cast<unsigned int*>(&b);
    return u;
}

// ---------------- zero counters/denominators ----------------
__global__ void zero_small_kernel() {
    int i = blockIdx.x * blockDim.x + threadIdx.x;
    if (i < NE) { g_cnt_e[i] = 0; g_den_e[i] = 0.f; }
    if (i < NV) { g_cnt_v[i] = 0; g_den_v[i] = 0.f; }
}

// ---------------- histogram + denominators ----------------
__global__ void count_den_kernel(const int* __restrict__ pv, const int* __restrict__ pe,
                                 const float* __restrict__ wv2e, const float* __restrict__ we2v) {
    int i = blockIdx.x * blockDim.x + threadIdx.x;
    if (i >= NNZp) return;
    int v = pv[i], e = pe[i];
    atomicAdd(&g_cnt_e[e], 1);
    atomicAdd(&g_den_e[e], wv2e[i]);
    atomicAdd(&g_cnt_v[v], 1);
    atomicAdd(&g_den_v[v], we2v[i]);
}

__global__ void invden_kernel() {
    int i = blockIdx.x * blockDim.x + threadIdx.x;
    if (i < NE) g_invdene[i] = 1.f / fmaxf(g_den_e[i], 1e-12f);
    if (i < NV) g_invdenv[i] = 1.f / fmaxf(g_den_v[i], 1e-12f);
}

// ---------------- scan (1024 elems per block) ----------------
__global__ void scan_chunk_kernel(const int* __restrict__ in, int* __restrict__ incl,
                                  int* __restrict__ bsums, int n) {
    __shared__ int sh[256];
    int t = threadIdx.x;
    int base = blockIdx.x * 1024 + t * 4;
    int a0 = (base + 0 < n) ? in[base + 0] : 0;
    int a1 = (base + 1 < n) ? in[base + 1] : 0;
    int a2 = (base + 2 < n) ? in[base + 2] : 0;
    int a3 = (base + 3 < n) ? in[base + 3] : 0;
    int s1 = a0 + a1, s2 = s1 + a2, s3 = s2 + a3;
    sh[t] = s3;
    __syncthreads();
#pragma unroll
    for (int o = 1; o < 256; o <<= 1) {
        int v = (t >= o) ? sh[t - o] : 0;
        __syncthreads();
        sh[t] += v;
        __syncthreads();
    }
    int excl = sh[t] - s3;
    if (base + 0 < n) incl[base + 0] = excl + a0;
    if (base + 1 < n) incl[base + 1] = excl + s1;
    if (base + 2 < n) incl[base + 2] = excl + s2;
    if (base + 3 < n) incl[base + 3] = excl + s3;
    if (t == 255) bsums[blockIdx.x] = sh[255];
}

__global__ void scan_bsums_kernel(int* __restrict__ bsums, int nb) {
    __shared__ int sh[256];
    int t = threadIdx.x;
    int v = (t < nb) ? bsums[t] : 0;
    sh[t] = v;
    __syncthreads();
#pragma unroll
    for (int o = 1; o < 256; o <<= 1) {
        int u = (t >= o) ? sh[t - o] : 0;
        __syncthreads();
        sh[t] += u;
        __syncthreads();
    }
    if (t < nb) bsums[t] = sh[t] - v;   // exclusive
}

__global__ void finalize_off_kernel(const int* __restrict__ incl, const int* __restrict__ bexcl,
                                    int* __restrict__ off, int* __restrict__ cur, int n) {
    int i = blockIdx.x * blockDim.x + threadIdx.x;
    if (i >= n) return;
    int val = incl[i] + bexcl[i >> 10];
    off[i + 1] = val;
    cur[i + 1] = val;
    if (i == 0) { off[0] = 0; cur[0] = 0; }
}

// ---------------- fill CSR-style permuted arrays ----------------
__global__ void fill_kernel(const int* __restrict__ pv, const int* __restrict__ pe,
                            const float* __restrict__ wv2e, const float* __restrict__ we2v) {
    int i = blockIdx.x * blockDim.x + threadIdx.x;
    if (i >= NNZp) return;
    int v = pv[i], e = pe[i];
    int pe_pos = atomicAdd(&g_cur_e[e], 1);
    g_esrc[pe_pos] = v;
    g_ew[pe_pos]   = wv2e[i];
    int pv_pos = atomicAdd(&g_cur_v[v], 1);
    g_vsrc[pv_pos] = e;
    g_vw[pv_pos]   = we2v[i];
}

// ---------------- W prep: transpose + bf16 hi/lo split ----------------
__global__ void wprep_kernel(const float* __restrict__ Wm) {
    int i = blockIdx.x * blockDim.x + threadIdx.x;  // over DD*FIN
    if (i >= DD * FIN) return;
    int n = i / FIN, k = i % FIN;
    float w = Wm[(size_t)k * DD + n];
    __nv_bfloat16 hi = __float2bfloat16_rn(w);
    __nv_bfloat16 lo = __float2bfloat16_rn(w - __bfloat162float(hi));
    g_Wth[i] = hi;
    g_Wtl[i] = lo;
}

// ---------------- bf16-split tensor-core GEMM:  xh0 = fp16(feats @ W + b) ----------------
// BM=128, BN=128(=DD), BK=32, 256 threads = 8 warps (4 m x 2 n), warp tile 32x64.
// A-stream register prefetch hides DRAM latency under MMA; B is tiny and L2-hot.
// C = Ah*Bh + Ah*Bl + Al*Bh  (fp32 accumulate; lo*lo dropped, err ~1e-5)
#define SK 40   // padded smem stride in halves (conflict-free)
#define NTILES (FIN / 32)
__global__ void __launch_bounds__(256, 2) gemm_bf16_kernel(const float* __restrict__ A,
                                                           const float* __restrict__ bias,
                                                           __half* __restrict__ C) {
    __shared__ __nv_bfloat16 Ah[128][SK], Al[128][SK];
    __shared__ __nv_bfloat16 Bh[128][SK], Bl[128][SK];

    const int tid  = threadIdx.x;
    const int lane = tid & 31;
    const int wid  = tid >> 5;
    const int warp_m = wid & 3;
    const int warp_n = wid >> 2;
    const int brow = blockIdx.x * 128;

    float acc[2][8][4];
#pragma unroll
    for (int mt = 0; mt < 2; mt++)
#pragma unroll
        for (int nt = 0; nt < 8; nt++)
#pragma unroll
            for (int q = 0; q < 4; q++) acc[mt][nt][q] = 0.f;

    const int arow = tid >> 3;            // 0..31 (+32*ii)
    const int acol = (tid & 7) * 4;
    const int bn   = tid >> 2;            // 0..63 (+64*ii)
    const int bseg = (tid & 3) * 8;

    float4 pre_a[4];

    auto load_a = [&](int k0) {
#pragma unroll
        for (int ii = 0; ii < 4; ii++) {
            int gr = brow + arow + ii * 32;
            pre_a[ii] = make_float4(0.f, 0.f, 0.f, 0.f);
            if (gr < NV) pre_a[ii] = *(const float4*)(A + (size_t)gr * FIN + k0 + acol);
        }
    };
    auto store_a = [&]() {
#pragma unroll
        for (int ii = 0; ii < 4; ii++) {
            int row = arow + ii * 32;
            float4 v = pre_a[ii];
            __nv_bfloat16 hx = __float2bfloat16_rn(v.x);
            __nv_bfloat16 hy = __float2bfloat16_rn(v.y);
            __nv_bfloat16 hz = __float2bfloat16_rn(v.z);
            __nv_bfloat16 hw = __float2bfloat16_rn(v.w);
            __nv_bfloat16 lx = __float2bfloat16_rn(v.x - __bfloat162float(hx));
            __nv_bfloat16 ly = __float2bfloat16_rn(v.y - __bfloat162float(hy));
            __nv_bfloat16 lz = __float2bfloat16_rn(v.z - __bfloat162float(hz));
            __nv_bfloat16 lw = __float2bfloat16_rn(v.w - __bfloat162float(hw));
            *(__nv_bfloat162*)&Ah[row][acol]     = __halves2bfloat162(hx, hy);
            *(__nv_bfloat162*)&Ah[row][acol + 2] = __halves2bfloat162(hz, hw);
            *(__nv_bfloat162*)&Al[row][acol]     = __halves2bfloat162(lx, ly);
            *(__nv_bfloat162*)&Al[row][acol + 2] = __halves2bfloat162(lz, lw);
        }
    };
    auto load_store_b = [&](int k0) {
#pragma unroll
        for (int ii = 0; ii < 2; ii++) {
            int n = bn + ii * 64;
            *(uint4*)&Bh[n][bseg] = *(const uint4*)&g_Wth[(size_t)n * FIN + k0 + bseg];
            *(uint4*)&Bl[n][bseg] = *(const uint4*)&g_Wtl[(size_t)n * FIN + k0 + bseg];
        }
    };

    load_a(0);
    store_a();
    load_store_b(0);
    __syncthreads();

    for (int t = 0; t < NTILES; t++) {
        if (t + 1 < NTILES) load_a((t + 1) * 32);   // LDGs in flight during compute

#pragma unroll
        for (int kk = 0; kk < 32; kk += 16) {
            const int c0 = kk + (lane & 3) * 2;
            const int ra = warp_m * 32 + (lane >> 2);
            unsigned int ah[2][4], al[2][4];
#pragma unroll
            for (int mt = 0; mt < 2; mt++) {
                int r = ra + mt * 16;
                ah[mt][0] = *(const unsigned int*)&Ah[r][c0];
                ah[mt][1] = *(const unsigned int*)&Ah[r + 8][c0];
                ah[mt][2] = *(const unsigned int*)&Ah[r][c0 + 8];
                ah[mt][3] = *(const unsigned int*)&Ah[r + 8][c0 + 8];
                al[mt][0] = *(const unsigned int*)&Al[r][c0];
                al[mt][1] = *(const unsigned int*)&Al[r + 8][c0];
                al[mt][2] = *(const unsigned int*)&Al[r][c0 + 8];
                al[mt][3] = *(const unsigned int*)&Al[r + 8][c0 + 8];
            }
#pragma unroll
            for (int nt = 0; nt < 8; nt++) {
                int n = warp_n * 64 + nt * 8 + (lane >> 2);
                unsigned int bh0 = *(const unsigned int*)&Bh[n][c0];
                unsigned int bh1 = *(const unsigned int*)&Bh[n][c0 + 8];
                unsigned int bl0 = *(const unsigned int*)&Bl[n][c0];
                unsigned int bl1 = *(const unsigned int*)&Bl[n][c0 + 8];
#pragma unroll
                for (int mt = 0; mt < 2; mt++) {
                    float* d = acc[mt][nt];
                    asm volatile("mma.sync.aligned.m16n8k16.row.col.f32.bf16.bf16.f32 "
                        "{%0,%1,%2,%3}, {%4,%5,%6,%7}, {%8,%9}, {%0,%1,%2,%3};"
                        : "+f"(d[0]), "+f"(d[1]), "+f"(d[2]), "+f"(d[3])
                        : "r"(ah[mt][0]), "r"(ah[mt][1]), "r"(ah[mt][2]), "r"(ah[mt][3]),
                          "r"(bh0), "r"(bh1));
                    asm volatile("mma.sync.aligned.m16n8k16.row.col.f32.bf16.bf16.f32 "
                        "{%0,%1,%2,%3}, {%4,%5,%6,%7}, {%8,%9}, {%0,%1,%2,%3};"
                        : "+f"(d[0]), "+f"(d[1]), "+f"(d[2]), "+f"(d[3])
                        : "r"(ah[mt][0]), "r"(ah[mt][1]), "r"(ah[mt][2]), "r"(ah[mt][3]),
                          "r"(bl0), "r"(bl1));
                    asm volatile("mma.sync.aligned.m16n8k16.row.col.f32.bf16.bf16.f32 "
                        "{%0,%1,%2,%3}, {%4,%5,%6,%7}, {%8,%9}, {%0,%1,%2,%3};"
                        : "+f"(d[0]), "+f"(d[1]), "+f"(d[2]), "+f"(d[3])
                        : "r"(al[mt][0]), "r"(al[mt][1]), "r"(al[mt][2]), "r"(al[mt][3]),
                          "r"(bh0), "r"(bh1));
                }
            }
        }
        __syncthreads();
        if (t + 1 < NTILES) {
            store_a();
            load_store_b((t + 1) * 32);
            __syncthreads();
        }
    }

    const int rbase = brow + warp_m * 32 + (lane >> 2);
    const int cbase = warp_n * 64 + (lane & 3) * 2;
#pragma unroll
    for (int nt = 0; nt < 8; nt++) {
        int col = cbase + nt * 8;
        float b0 = __ldg(bias + col);
        float b1 = __ldg(bias + col + 1);
#pragma unroll
        for (int mt = 0; mt < 2; mt++) {
            int r0 = rbase + mt * 16;
            if (r0 < NV) {
                __half2 o = __floats2half2_rn(acc[mt][nt][0] + b0, acc[mt][nt][1] + b1);
                *(__half2*)(C + (size_t)r0 * DD + col) = o;
            }
            int r1 = r0 + 8;
            if (r1 < NV) {
                __half2 o = __floats2half2_rn(acc[mt][nt][2] + b0, acc[mt][nt][3] + b1);
                *(__half2*)(C + (size_t)r1 * DD + col) = o;
            }
        }
    }
}

// ---------------- gather-based weighted-mean aggregation (fp16 src/dst, fp32 math) ----------------
__global__ void __launch_bounds__(256) agg_kernel_h(const __half* __restrict__ src,
                                                    __half* __restrict__ dst,
                                                    const int* __restrict__ off,
                                                    const int* __restrict__ sidx,
                                                    const float* __restrict__ wt,
                                                    const float* __restrict__ invden,
                                                    int ndst) {
    int t = blockIdx.x * blockDim.x + threadIdx.x;
    int r = t >> 5;
    int lane = t & 31;
    if (r >= ndst) return;
    int j0 = __ldg(off + r);
    int j1 = __ldg(off + r + 1);
    float4 acc = make_float4(0.f, 0.f, 0.f, 0.f);
    const int cofs = lane * 4;
    int j = j0;
    for (; j + 4 <= j1; j += 4) {
        int   s0 = __ldg(sidx + j),     s1 = __ldg(sidx + j + 1);
        int   s2 = __ldg(sidx + j + 2), s3 = __ldg(sidx + j + 3);
        float w0 = __ldg(wt + j),       w1 = __ldg(wt + j + 1);
        float w2 = __ldg(wt + j + 2),   w3 = __ldg(wt + j + 3);
        float4 v0 = h4_to_f4(*(const uint2*)(src + (size_t)s0 * DD + cofs));
        float4 v1 = h4_to_f4(*(const uint2*)(src + (size_t)s1 * DD + cofs));
        float4 v2 = h4_to_f4(*(const uint2*)(src + (size_t)s2 * DD + cofs));
        float4 v3 = h4_to_f4(*(const uint2*)(src + (size_t)s3 * DD + cofs));
        acc.x = fmaf(w0, v0.x, acc.x); acc.y = fmaf(w0, v0.y, acc.y);
        acc.z = fmaf(w0, v0.z, acc.z); acc.w = fmaf(w0, v0.w, acc.w);
        acc.x = fmaf(w1, v1.x, acc.x); acc.y = fmaf(w1, v1.y, acc.y);
        acc.z = fmaf(w1, v1.z, acc.z); acc.w = fmaf(w1, v1.w, acc.w);
        acc.x = fmaf(w2, v2.x, acc.x); acc.y = fmaf(w2, v2.y, acc.y);
        acc.z = fmaf(w2, v2.z, acc.z); acc.w = fmaf(w2, v2.w, acc.w);
        acc.x = fmaf(w3, v3.x, acc.x); acc.y = fmaf(w3, v3.y, acc.y);
        acc.z = fmaf(w3, v3.z, acc.z); acc.w = fmaf(w3, v3.w, acc.w);
    }
    for (; j < j1; j++) {
        int   s0 = __ldg(sidx + j);
        float w0 = __ldg(wt + j);
        float4 v0 = h4_to_f4(*(const uint2*)(src + (size_t)s0 * DD + cofs));
        acc.x = fmaf(w0, v0.x, acc.x); acc.y = fmaf(w0, v0.y, acc.y);
        acc.z = fmaf(w0, v0.z, acc.z); acc.w = fmaf(w0, v0.w, acc.w);
    }
    float sc = __ldg(invden + r);
    acc.x *= sc; acc.y *= sc; acc.z *= sc; acc.w *= sc;
    *(uint2*)(dst + (size_t)r * DD + cofs) = f4_to_h4(acc);
}

// ---------------- final agg fused with softmax (fp16 src, fp32 out) ----------------
__global__ void __launch_bounds__(256) agg_softmax_kernel_h(const __half* __restrict__ src,
                                                            float4* __restrict__ out,
                                                            const int* __restrict__ off,
                                                            const int* __restrict__ sidx,
                                                            const float* __restrict__ wt,
                                                            const float* __restrict__ invden) {
    int t = blockIdx.x * blockDim.x + threadIdx.x;
    int r = t >> 5;
    int lane = t & 31;
    if (r >= NV) return;
    int j0 = __ldg(off + r);
    int j1 = __ldg(off + r + 1);
    float4 acc = make_float4(0.f, 0.f, 0.f, 0.f);
    const int cofs = lane * 4;
    int j = j0;
    for (; j + 4 <= j1; j += 4) {
        int   s0 = __ldg(sidx + j),     s1 = __ldg(sidx + j + 1);
        int   s2 = __ldg(sidx + j + 2), s3 = __ldg(sidx + j + 3);
        float w0 = __ldg(wt + j),       w1 = __ldg(wt + j + 1);
        float w2 = __ldg(wt + j + 2),   w3 = __ldg(wt + j + 3);
        float4 v0 = h4_to_f4(*(const uint2*)(src + (size_t)s0 * DD + cofs));
        float4 v1 = h4_to_f4(*(const uint2*)(src + (size_t)s1 * DD + cofs));
        float4 v2 = h4_to_f4(*(const uint2*)(src + (size_t)s2 * DD + cofs));
        float4 v3 = h4_to_f4(*(const uint2*)(src + (size_t)s3 * DD + cofs));
        acc.x = fmaf(w0, v0.x, acc.x); acc.y = fmaf(w0, v0.y, acc.y);
        acc.z = fmaf(w0, v0.z, acc.z); acc.w = fmaf(w0, v0.w, acc.w);
        acc.x = fmaf(w1, v1.x, acc.x); acc.y = fmaf(w1, v1.y, acc.y);
        acc.z = fmaf(w1, v1.z, acc.z); acc.w = fmaf(w1, v1.w, acc.w);
        acc.x = fmaf(w2, v2.x, acc.x); acc.y = fmaf(w2, v2.y, acc.y);
        acc.z = fmaf(w2, v2.z, acc.z); acc.w = fmaf(w2, v2.w, acc.w);
        acc.x = fmaf(w3, v3.x, acc.x); acc.y = fmaf(w3, v3.y, acc.y);
        acc.z = fmaf(w3, v3.z, acc.z); acc.w = fmaf(w3, v3.w, acc.w);
    }
    for (; j < j1; j++) {
        int   s0 = __ldg(sidx + j);
        float w0 = __ldg(wt + j);
        float4 v0 = h4_to_f4(*(const uint2*)(src + (size_t)s0 * DD + cofs));
        acc.x = fmaf(w0, v0.x, acc.x); acc.y = fmaf(w0, v0.y, acc.y);
        acc.z = fmaf(w0, v0.z, acc.z); acc.w = fmaf(w0, v0.w, acc.w);
    }
    float sc = __ldg(invden + r);
    acc.x *= sc; acc.y *= sc; acc.z *= sc; acc.w *= sc;
    // warp softmax over the 128 values
    float m = fmaxf(fmaxf(acc.x, acc.y), fmaxf(acc.z, acc.w));
#pragma unroll
    for (int o = 16; o; o >>= 1) m = fmaxf(m, __shfl_xor_sync(0xffffffffu, m, o));
    float4 e;
    e.x = __expf(acc.x - m); e.y = __expf(acc.y - m);
    e.z = __expf(acc.z - m); e.w = __expf(acc.w - m);
    float s = e.x + e.y + e.z + e.w;
#pragma unroll
    for (int o = 16; o; o >>= 1) s += __shfl_xor_sync(0xffffffffu, s, o);
    float inv = 1.f / s;
    out[(size_t)r * 32 + lane] = make_float4(e.x * inv, e.y * inv, e.z * inv, e.w * inv);
}

// ---------------- launch ----------------
extern "C" void kernel_launch(void* const* d_in, const int* in_sizes, int n_in,
                              void* d_out, int out_size) {
    const float* feats = (const float*)d_in[0];
    const float* Wm    = (const float*)d_in[1];
    const float* bias  = (const float*)d_in[2];
    const float* v2e_w = (const float*)d_in[3];
    const float* e2v_w = (const float*)d_in[4];
    const int*   pv    = (const int*)d_in[5];
    const int*   pe    = (const int*)d_in[6];
    float* out = (float*)d_out;

    __half *xh0, *x1h, *yh;
    float *invdene, *invdenv, *ew, *vw;
    int *cnt_e, *cnt_v, *off_e, *off_v, *cur_e, *cur_v, *esrc, *vsrc, *scan_tmp, *bsums;
    cudaGetSymbolAddress((void**)&xh0, g_xh0);
    cudaGetSymbolAddress((void**)&x1h, g_x1h);
    cudaGetSymbolAddress((void**)&yh,  g_yh);
    cudaGetSymbolAddress((void**)&invdene, g_invdene);
    cudaGetSymbolAddress((void**)&invdenv, g_invdenv);
    cudaGetSymbolAddress((void**)&ew, g_ew);
    cudaGetSymbolAddress((void**)&vw, g_vw);
    cudaGetSymbolAddress((void**)&cnt_e, g_cnt_e);
    cudaGetSymbolAddress((void**)&cnt_v, g_cnt_v);
    cudaGetSymbolAddress((void**)&off_e, g_off_e);
    cudaGetSymbolAddress((void**)&off_v, g_off_v);
    cudaGetSymbolAddress((void**)&cur_e, g_cur_e);
    cudaGetSymbolAddress((void**)&cur_v, g_cur_v);
    cudaGetSymbolAddress((void**)&esrc, g_esrc);
    cudaGetSymbolAddress((void**)&vsrc, g_vsrc);
    cudaGetSymbolAddress((void**)&scan_tmp, g_scan_tmp);
    cudaGetSymbolAddress((void**)&bsums, g_bsums);

    const int TB = 256;
    const int nnzBlocks = (NNZp + TB - 1) / TB;

    // Fork a side stream for the CSR build chain; GEMM runs on the main (captured)
    // stream concurrently. Standard capture-fork: event edges define the graph deps.
    cudaStream_t s2;
    cudaStreamCreateWithFlags(&s2, cudaStreamNonBlocking);
    cudaEvent_t evFork, evJoin;
    cudaEventCreateWithFlags(&evFork, cudaEventDisableTiming);
    cudaEventCreateWithFlags(&evJoin, cudaEventDisableTiming);

    cudaEventRecord(evFork, 0);
    cudaStreamWaitEvent(s2, evFork, 0);

    // ---- branch A (s2): CSR build ----
    zero_small_kernel<<<(NV + TB - 1) / TB, TB, 0, s2>>>();
    count_den_kernel<<<nnzBlocks, TB, 0, s2>>>(pv, pe, v2e_w, e2v_w);
    invden_kernel<<<(NV + TB - 1) / TB, TB, 0, s2>>>();
    {
        int nb = (NE + 1023) / 1024;
        scan_chunk_kernel<<<nb, 256, 0, s2>>>(cnt_e, scan_tmp, bsums, NE);
        scan_bsums_kernel<<<1, 256, 0, s2>>>(bsums, nb);
        finalize_off_kernel<<<(NE + TB - 1) / TB, TB, 0, s2>>>(scan_tmp, bsums, off_e, cur_e, NE);
    }
    {
        int nb = (NV + 1023) / 1024;
        scan_chunk_kernel<<<nb, 256, 0, s2>>>(cnt_v, scan_tmp, bsums, NV);
        scan_bsums_kernel<<<1, 256, 0, s2>>>(bsums, nb);
        finalize_off_kernel<<<(NV + TB - 1) / TB, TB, 0, s2>>>(scan_tmp, bsums, off_v, cur_v, NV);
    }
    fill_kernel<<<nnzBlocks, TB, 0, s2>>>(pv, pe, v2e_w, e2v_w);

    // ---- branch B (main stream): W prep + GEMM ----
    wprep_kernel<<<(DD * FIN + TB - 1) / TB, TB>>>(Wm);
    gemm_bf16_kernel<<<(NV + 127) / 128, TB>>>(feats, bias, xh0);

    // ---- join ----
    cudaEventRecord(evJoin, s2);
    cudaStreamWaitEvent(0, evJoin, 0);

    // 5) two hops of weighted-mean aggregation (fp16 features, fp32 math);
    //    last pass fused with softmax
    const int eBlocks = (NE * 32) / TB;
    const int vBlocks = (NV * 32) / TB;
    agg_kernel_h<<<eBlocks, TB>>>(xh0, yh,  off_e, esrc, ew, invdene, NE);
    agg_kernel_h<<<vBlocks, TB>>>(yh,  x1h, off_v, vsrc, vw, invdenv, NV);
    agg_kernel_h<<<eBlocks, TB>>>(x1h, yh,  off_e, esrc, ew, invdene, NE);
    agg_softmax_kernel_h<<<vBlocks, TB>>>(yh, (float4*)out, off_v, vsrc, vw, invdenv);
}